// round 1
// baseline (speedup 1.0000x reference)
#include <cuda_runtime.h>

#define N_IN_CH   256
#define N_OUT_CH  3
#define N_WDIM    512
#define N_BATCH   8

// styles[b][c], produced by kernel A, consumed by kernel B
__device__ float g_styles[N_BATCH * N_IN_CH];

// ---------------------------------------------------------------------------
// Kernel A: styles[b][c] = (dot(w[b,:], affine_W[c,:]) * (1/sqrt(512)) + affine_b[c]) / 16
// one warp per (b, c) pair; 2048 warps total.
// ---------------------------------------------------------------------------
__global__ void styles_kernel(const float* __restrict__ w,
                              const float* __restrict__ affine_W,
                              const float* __restrict__ affine_b) {
    int gw   = (blockIdx.x * blockDim.x + threadIdx.x) >> 5;
    int lane = threadIdx.x & 31;
    if (gw >= N_BATCH * N_IN_CH) return;
    int b = gw >> 8;     // / 256
    int c = gw & 255;

    const float* wr = w + (size_t)b * N_WDIM;
    const float* ar = affine_W + (size_t)c * N_WDIM;

    float s = 0.f;
#pragma unroll
    for (int i = 0; i < N_WDIM / 32; ++i) {
        int k = lane + 32 * i;
        s += wr[k] * ar[k];
    }
#pragma unroll
    for (int off = 16; off; off >>= 1)
        s += __shfl_down_sync(0xffffffffu, s, off);

    if (lane == 0) {
        const float affine_gain = 0.04419417382415922f;  // 1/sqrt(512)
        const float weight_gain = 0.0625f;               // 1/sqrt(256*1^3)
        g_styles[gw] = (s * affine_gain + affine_b[c]) * weight_gain;
    }
}

// ---------------------------------------------------------------------------
// Kernel B: warp-per-point, 2-point unroll.
//   out[p,o] = clip( sum_c x[p,c] * style[b(p),c] * convW[c,o] + convb[o] )
// Lane l owns channels {4l..4l+3} and {128+4l..128+4l+3}.
// conv_W rows live in registers (batch-independent); styles live in smem.
// ---------------------------------------------------------------------------
__global__ void __launch_bounds__(256, 3)
modconv_kernel(const float4* __restrict__ xf,      // (n, 64) float4 view of (n,256)
               const int*    __restrict__ coord,   // (n, 4) int32, col 0 = batch idx
               const float*  __restrict__ convW,   // (256, 3)
               const float*  __restrict__ convb,   // (3,)
               float*        __restrict__ out,     // (n, 3)
               int n) {
    __shared__ float s_style[N_BATCH * N_IN_CH];   // 8 KB
    for (int i = threadIdx.x; i < N_BATCH * N_IN_CH; i += blockDim.x)
        s_style[i] = g_styles[i];

    int lane = threadIdx.x & 31;

    // conv_W rows for this lane's 8 channels
    float wreg[8][3];
#pragma unroll
    for (int j = 0; j < 8; ++j) {
        int c = (j < 4) ? (lane * 4 + j) : (128 + lane * 4 + (j - 4));
        wreg[j][0] = convW[c * 3 + 0];
        wreg[j][1] = convW[c * 3 + 1];
        wreg[j][2] = convW[c * 3 + 2];
    }
    float bb0 = convb[0], bb1 = convb[1], bb2 = convb[2];

    __syncthreads();

    int warp   = (blockIdx.x * blockDim.x + threadIdx.x) >> 5;
    int nwarps = (gridDim.x * blockDim.x) >> 5;

#define ACC3(m, j, A0, A1, A2)        \
    do {                              \
        A0 += (m) * wreg[j][0];       \
        A1 += (m) * wreg[j][1];       \
        A2 += (m) * wreg[j][2];       \
    } while (0)

    for (int p0 = warp * 2; p0 < n; p0 += nwarps * 2) {
        int p1   = p0 + 1;
        bool do1 = (p1 < n);

        int b0 = __ldg(coord + (size_t)p0 * 4);
        int b1 = do1 ? __ldg(coord + (size_t)p1 * 4) : 0;

        const float4* r0 = xf + (size_t)p0 * 64;
        const float4* r1 = xf + (size_t)p1 * 64;

        float4 x0a = r0[lane];
        float4 x0b = r0[lane + 32];
        float4 x1a = make_float4(0.f, 0.f, 0.f, 0.f);
        float4 x1b = x1a;
        if (do1) { x1a = r1[lane]; x1b = r1[lane + 32]; }

        const float* st0 = s_style + b0 * N_IN_CH;
        const float* st1 = s_style + b1 * N_IN_CH;
        float4 s0a = *(const float4*)(st0 + lane * 4);
        float4 s0b = *(const float4*)(st0 + 128 + lane * 4);
        float4 s1a = *(const float4*)(st1 + lane * 4);
        float4 s1b = *(const float4*)(st1 + 128 + lane * 4);

        float a00 = 0.f, a01 = 0.f, a02 = 0.f;
        float a10 = 0.f, a11 = 0.f, a12 = 0.f;
        float m;

        m = x0a.x * s0a.x; ACC3(m, 0, a00, a01, a02);
        m = x0a.y * s0a.y; ACC3(m, 1, a00, a01, a02);
        m = x0a.z * s0a.z; ACC3(m, 2, a00, a01, a02);
        m = x0a.w * s0a.w; ACC3(m, 3, a00, a01, a02);
        m = x0b.x * s0b.x; ACC3(m, 4, a00, a01, a02);
        m = x0b.y * s0b.y; ACC3(m, 5, a00, a01, a02);
        m = x0b.z * s0b.z; ACC3(m, 6, a00, a01, a02);
        m = x0b.w * s0b.w; ACC3(m, 7, a00, a01, a02);

        m = x1a.x * s1a.x; ACC3(m, 0, a10, a11, a12);
        m = x1a.y * s1a.y; ACC3(m, 1, a10, a11, a12);
        m = x1a.z * s1a.z; ACC3(m, 2, a10, a11, a12);
        m = x1a.w * s1a.w; ACC3(m, 3, a10, a11, a12);
        m = x1b.x * s1b.x; ACC3(m, 4, a10, a11, a12);
        m = x1b.y * s1b.y; ACC3(m, 5, a10, a11, a12);
        m = x1b.z * s1b.z; ACC3(m, 6, a10, a11, a12);
        m = x1b.w * s1b.w; ACC3(m, 7, a10, a11, a12);

#pragma unroll
        for (int off = 16; off; off >>= 1) {
            a00 += __shfl_down_sync(0xffffffffu, a00, off);
            a01 += __shfl_down_sync(0xffffffffu, a01, off);
            a02 += __shfl_down_sync(0xffffffffu, a02, off);
            a10 += __shfl_down_sync(0xffffffffu, a10, off);
            a11 += __shfl_down_sync(0xffffffffu, a11, off);
            a12 += __shfl_down_sync(0xffffffffu, a12, off);
        }

        if (lane == 0) {
            float o0 = fminf(fmaxf(a00 + bb0, -256.f), 256.f);
            float o1 = fminf(fmaxf(a01 + bb1, -256.f), 256.f);
            float o2 = fminf(fmaxf(a02 + bb2, -256.f), 256.f);
            out[(size_t)p0 * 3 + 0] = o0;
            out[(size_t)p0 * 3 + 1] = o1;
            out[(size_t)p0 * 3 + 2] = o2;
            if (do1) {
                float q0 = fminf(fmaxf(a10 + bb0, -256.f), 256.f);
                float q1 = fminf(fmaxf(a11 + bb1, -256.f), 256.f);
                float q2 = fminf(fmaxf(a12 + bb2, -256.f), 256.f);
                out[(size_t)p1 * 3 + 0] = q0;
                out[(size_t)p1 * 3 + 1] = q1;
                out[(size_t)p1 * 3 + 2] = q2;
            }
        }
    }
#undef ACC3
}

// ---------------------------------------------------------------------------
// kernel_launch
// inputs (metadata order): x_feat, x_coord, w, affine_W, affine_b, conv_W, conv_b
// ---------------------------------------------------------------------------
extern "C" void kernel_launch(void* const* d_in, const int* in_sizes, int n_in,
                              void* d_out, int out_size) {
    const float* x_feat   = (const float*)d_in[0];
    const int*   x_coord  = (const int*)  d_in[1];
    const float* w        = (const float*)d_in[2];
    const float* affine_W = (const float*)d_in[3];
    const float* affine_b = (const float*)d_in[4];
    const float* conv_W   = (const float*)d_in[5];
    const float* conv_b   = (const float*)d_in[6];
    float* out = (float*)d_out;

    int n = in_sizes[0] / N_IN_CH;   // number of points

    // Kernel A: 2048 warps -> 256 blocks x 256 threads
    styles_kernel<<<256, 256>>>(w, affine_W, affine_b);

    // Kernel B: grid-stride, ~3 blocks/SM resident
    int blocks = 148 * 3;
    modconv_kernel<<<blocks, 256>>>((const float4*)x_feat, x_coord,
                                    conv_W, conv_b, out, n);
}

// round 2
// speedup vs baseline: 1.1487x; 1.1487x over previous
#include <cuda_runtime.h>

#define N_IN_CH   256
#define N_OUT_CH  3
#define N_WDIM    512
#define N_BATCH   8

// styles[b][c], produced by kernel A, consumed by kernel B
__device__ float g_styles[N_BATCH * N_IN_CH];

// ---------------------------------------------------------------------------
// Kernel A: styles[b][c] = (dot(w[b,:], affine_W[c,:]) / sqrt(512) + affine_b[c]) / 16
// one warp per (b, c) pair; 2048 warps total.
// ---------------------------------------------------------------------------
__global__ void styles_kernel(const float* __restrict__ w,
                              const float* __restrict__ affine_W,
                              const float* __restrict__ affine_b) {
    int gw   = (blockIdx.x * blockDim.x + threadIdx.x) >> 5;
    int lane = threadIdx.x & 31;
    if (gw >= N_BATCH * N_IN_CH) return;
    int b = gw >> 8;
    int c = gw & 255;

    const float* wr = w + (size_t)b * N_WDIM;
    const float* ar = affine_W + (size_t)c * N_WDIM;

    float s = 0.f;
#pragma unroll
    for (int i = 0; i < N_WDIM / 32; ++i) {
        int k = lane + 32 * i;
        s += wr[k] * ar[k];
    }
#pragma unroll
    for (int off = 16; off; off >>= 1)
        s += __shfl_down_sync(0xffffffffu, s, off);

    if (lane == 0) {
        const float affine_gain = 0.04419417382415922f;  // 1/sqrt(512)
        const float weight_gain = 0.0625f;               // 1/sqrt(256)
        g_styles[gw] = (s * affine_gain + affine_b[c]) * weight_gain;
    }
}

// ---------------------------------------------------------------------------
// Kernel B: warp-per-point-pair, software-pipelined (double-buffered loads).
// Lane l owns channels {4l..4l+3} and {128+4l..128+4l+3}.
// conv_W rows live in registers; styles in smem; x loads stream (__ldcs).
// ---------------------------------------------------------------------------
__global__ void __launch_bounds__(256, 3)
modconv_kernel(const float4* __restrict__ xf,      // (n, 64) float4 view of (n,256)
               const int*    __restrict__ coord,   // (n, 4), col 0 = batch idx
               const float*  __restrict__ convW,   // (256, 3)
               const float*  __restrict__ convb,   // (3,)
               float*        __restrict__ out,     // (n, 3)
               int n) {
    __shared__ float s_style[N_BATCH * N_IN_CH];   // 8 KB
    for (int i = threadIdx.x; i < N_BATCH * N_IN_CH; i += blockDim.x)
        s_style[i] = g_styles[i];

    int lane = threadIdx.x & 31;

    float wreg[8][3];
#pragma unroll
    for (int j = 0; j < 8; ++j) {
        int c = (j < 4) ? (lane * 4 + j) : (128 + lane * 4 + (j - 4));
        wreg[j][0] = convW[c * 3 + 0];
        wreg[j][1] = convW[c * 3 + 1];
        wreg[j][2] = convW[c * 3 + 2];
    }
    float bb0 = convb[0], bb1 = convb[1], bb2 = convb[2];

    __syncthreads();

    int warp   = (blockIdx.x * blockDim.x + threadIdx.x) >> 5;
    int nwarps = (gridDim.x * blockDim.x) >> 5;
    int stride = nwarps * 2;

    int p = warp * 2;
    if (p >= n) return;

    // ---- prefetch state (the "next" buffer) ----
    int    nb0, nb1;
    float4 nxa0, nxb0, nxa1, nxb1;

#define PREFETCH(P)                                                         \
    do {                                                                    \
        int q0 = (P);                                                       \
        int q1 = q0 + 1; if (q1 >= n) q1 = n - 1;                           \
        nb0 = __ldg(coord + (size_t)q0 * 4);                                \
        nb1 = __ldg(coord + (size_t)q1 * 4);                                \
        const float4* r0 = xf + (size_t)q0 * 64;                            \
        const float4* r1 = xf + (size_t)q1 * 64;                            \
        nxa0 = __ldcs(r0 + lane);                                           \
        nxb0 = __ldcs(r0 + lane + 32);                                      \
        nxa1 = __ldcs(r1 + lane);                                           \
        nxb1 = __ldcs(r1 + lane + 32);                                      \
    } while (0)

#define ACC3(m, j, A0, A1, A2)        \
    do {                              \
        A0 += (m) * wreg[j][0];       \
        A1 += (m) * wreg[j][1];       \
        A2 += (m) * wreg[j][2];       \
    } while (0)

    PREFETCH(p);

    while (p < n) {
        // rotate next -> current
        int    b0 = nb0, b1 = nb1;
        float4 xa0 = nxa0, xb0 = nxb0, xa1 = nxa1, xb1 = nxb1;

        int pn = p + stride;
        if (pn < n) PREFETCH(pn);   // issue next pair's loads BEFORE compute

        const float* st0 = s_style + b0 * N_IN_CH;
        const float* st1 = s_style + b1 * N_IN_CH;

        float a00 = 0.f, a01 = 0.f, a02 = 0.f;
        float a10 = 0.f, a11 = 0.f, a12 = 0.f;
        float m;
        float4 s;

        s = *(const float4*)(st0 + lane * 4);
        m = xa0.x * s.x; ACC3(m, 0, a00, a01, a02);
        m = xa0.y * s.y; ACC3(m, 1, a00, a01, a02);
        m = xa0.z * s.z; ACC3(m, 2, a00, a01, a02);
        m = xa0.w * s.w; ACC3(m, 3, a00, a01, a02);
        s = *(const float4*)(st0 + 128 + lane * 4);
        m = xb0.x * s.x; ACC3(m, 4, a00, a01, a02);
        m = xb0.y * s.y; ACC3(m, 5, a00, a01, a02);
        m = xb0.z * s.z; ACC3(m, 6, a00, a01, a02);
        m = xb0.w * s.w; ACC3(m, 7, a00, a01, a02);

        s = *(const float4*)(st1 + lane * 4);
        m = xa1.x * s.x; ACC3(m, 0, a10, a11, a12);
        m = xa1.y * s.y; ACC3(m, 1, a10, a11, a12);
        m = xa1.z * s.z; ACC3(m, 2, a10, a11, a12);
        m = xa1.w * s.w; ACC3(m, 3, a10, a11, a12);
        s = *(const float4*)(st1 + 128 + lane * 4);
        m = xb1.x * s.x; ACC3(m, 4, a10, a11, a12);
        m = xb1.y * s.y; ACC3(m, 5, a10, a11, a12);
        m = xb1.z * s.z; ACC3(m, 6, a10, a11, a12);
        m = xb1.w * s.w; ACC3(m, 7, a10, a11, a12);

#pragma unroll
        for (int off = 16; off; off >>= 1) {
            a00 += __shfl_down_sync(0xffffffffu, a00, off);
            a01 += __shfl_down_sync(0xffffffffu, a01, off);
            a02 += __shfl_down_sync(0xffffffffu, a02, off);
            a10 += __shfl_down_sync(0xffffffffu, a10, off);
            a11 += __shfl_down_sync(0xffffffffu, a11, off);
            a12 += __shfl_down_sync(0xffffffffu, a12, off);
        }

        if (lane == 0) {
            float o0 = fminf(fmaxf(a00 + bb0, -256.f), 256.f);
            float o1 = fminf(fmaxf(a01 + bb1, -256.f), 256.f);
            float o2 = fminf(fmaxf(a02 + bb2, -256.f), 256.f);
            float q0 = fminf(fmaxf(a10 + bb0, -256.f), 256.f);
            float q1 = fminf(fmaxf(a11 + bb1, -256.f), 256.f);
            float q2 = fminf(fmaxf(a12 + bb2, -256.f), 256.f);
            float* o = out + (size_t)p * 3;     // p even -> 8B-aligned
            if (p + 1 < n) {
                ((float2*)o)[0] = make_float2(o0, o1);
                ((float2*)o)[1] = make_float2(o2, q0);
                ((float2*)o)[2] = make_float2(q1, q2);
            } else {
                o[0] = o0; o[1] = o1; o[2] = o2;
            }
        }
        p = pn;
    }
#undef ACC3
#undef PREFETCH
}

// ---------------------------------------------------------------------------
// kernel_launch
// inputs (metadata order): x_feat, x_coord, w, affine_W, affine_b, conv_W, conv_b
// ---------------------------------------------------------------------------
extern "C" void kernel_launch(void* const* d_in, const int* in_sizes, int n_in,
                              void* d_out, int out_size) {
    const float* x_feat   = (const float*)d_in[0];
    const int*   x_coord  = (const int*)  d_in[1];
    const float* w        = (const float*)d_in[2];
    const float* affine_W = (const float*)d_in[3];
    const float* affine_b = (const float*)d_in[4];
    const float* conv_W   = (const float*)d_in[5];
    const float* conv_b   = (const float*)d_in[6];
    float* out = (float*)d_out;

    int n = in_sizes[0] / N_IN_CH;

    styles_kernel<<<256, 256>>>(w, affine_W, affine_b);

    int blocks = 148 * 3;
    modconv_kernel<<<blocks, 256>>>((const float4*)x_feat, x_coord,
                                    conv_W, conv_b, out, n);
}